// round 1
// baseline (speedup 1.0000x reference)
#include <cuda_runtime.h>
#include <cuda_bf16.h>

// DecayModel: out[b,s,h] = (fwd[s] + bwd[s]) / norm[s] per (b,h) column,
// fwd[s] = sum_{k<=s} 0.5^{s-k} x[k], bwd[s] = sum_{k>=s} 0.5^{k-s} x[k],
// norm[s] = 4 - 2^{-s} - 2^{-(S-1-s)}.
//
// Decomposition: decay 0.5 => contributions beyond W=32 are < 2^-32 (rel),
// so each S-chunk of C=256 is computed independently with a W-halo warmup.
// Tile (C+2W) x 64 columns lives in shared memory; fwd partials round-trip
// through global out (L2-hot, block-private).

#define S_DIM 2048
#define H_DIM 1024
#define CHUNK 256
#define HALO  32
#define HTILE 64
#define ROWS  (CHUNK + 2 * HALO)   // 320

__global__ __launch_bounds__(HTILE, 2)
void decay_model_kernel(const float* __restrict__ x, float* __restrict__ out) {
    extern __shared__ float sm[];
    float* tile = sm;                      // ROWS * HTILE
    float* invn = sm + ROWS * HTILE;       // CHUNK

    const int tid   = threadIdx.x;
    const int s0    = blockIdx.x * CHUNK;
    const int h0    = blockIdx.y * HTILE;
    const int b     = blockIdx.z;

    const float* xb = x   + (size_t)b * S_DIM * H_DIM;
    float*       ob = out + (size_t)b * S_DIM * H_DIM;

    // ---- Cooperative vectorized tile load (zero-fill outside [0,S)) ----
    // Each row r holds x[s0 - HALO + r, h0 : h0+HTILE). 16 float4 per row.
    #pragma unroll 4
    for (int i = tid; i < ROWS * (HTILE / 4); i += HTILE) {
        int r  = i >> 4;            // / (HTILE/4)
        int c4 = i & 15;            // % (HTILE/4)
        int s  = s0 - HALO + r;
        float4 v = make_float4(0.f, 0.f, 0.f, 0.f);
        if (s >= 0 && s < S_DIM) {
            v = *reinterpret_cast<const float4*>(xb + (size_t)s * H_DIM + h0 + c4 * 4);
        }
        reinterpret_cast<float4*>(tile + r * HTILE)[c4] = v;
    }

    // ---- Per-chunk exact inverse norm (exp2f is exact here: d = 0.5) ----
    #pragma unroll
    for (int i = tid; i < CHUNK; i += HTILE) {
        int s = s0 + i;
        float norm = 4.0f - exp2f(-(float)s) - exp2f(-(float)(S_DIM - 1 - s));
        invn[i] = 1.0f / norm;
    }
    __syncthreads();

    const float* col  = tile + tid;                       // this thread's column
    float*       orow = ob + (size_t)s0 * H_DIM + h0 + tid;

    // ---- Forward scan: warmup over left halo, then C live elements ----
    float y = 0.0f;
    #pragma unroll 8
    for (int t = 0; t < HALO; ++t)
        y = fmaf(y, 0.5f, col[t * HTILE]);

    #pragma unroll 4
    for (int t = 0; t < CHUNK; ++t) {
        y = fmaf(y, 0.5f, col[(t + HALO) * HTILE]);
        orow[(size_t)t * H_DIM] = y;                      // fwd partial -> global (L2)
    }

    // ---- Backward scan: warmup over right halo, then combine + normalize ----
    float z = 0.0f;
    #pragma unroll 8
    for (int t = 0; t < HALO; ++t)
        z = fmaf(z, 0.5f, col[(ROWS - 1 - t) * HTILE]);

    #pragma unroll 4
    for (int t = CHUNK - 1; t >= 0; --t) {
        z = fmaf(z, 0.5f, col[(t + HALO) * HTILE]);
        float f = orow[(size_t)t * H_DIM];                // L2-hot re-read
        orow[(size_t)t * H_DIM] = (f + z) * invn[t];
    }
}

extern "C" void kernel_launch(void* const* d_in, const int* in_sizes, int n_in,
                              void* d_out, int out_size) {
    const float* x = (const float*)d_in[0];
    float* out = (float*)d_out;

    const int B = in_sizes[0] / (S_DIM * H_DIM);

    const int smem_bytes = (ROWS * HTILE + CHUNK) * (int)sizeof(float);
    static_assert(ROWS * HTILE * 4 <= 96 * 1024, "smem budget");

    cudaFuncSetAttribute(decay_model_kernel,
                         cudaFuncAttributeMaxDynamicSharedMemorySize, smem_bytes);

    dim3 grid(S_DIM / CHUNK, H_DIM / HTILE, B);   // (8, 16, B)
    decay_model_kernel<<<grid, HTILE, smem_bytes>>>(x, out);
}

// round 2
// speedup vs baseline: 3.8745x; 3.8745x over previous
#include <cuda_runtime.h>
#include <cuda_bf16.h>

// DecayModel: out[b,s,h] = (fwd[s] + bwd[s]) / norm[s] per (b,h) column.
// fwd[s] = sum_{k<=s} 0.5^{s-k} x[k];  bwd[s] = sum_{k>=s} 0.5^{k-s} x[k];
// norm[s] = 4 - 2^-s - 2^-(S-1-s)  (== 4.0f exactly in fp32 for 22<=s<=S-23).
//
// Strategy: chunk S into independent 64-element pieces with a 24-element decay
// halo (truncation < 2^-24 relative). Per thread: one (b,h) column, one chunk.
// Warp spans 32 consecutive h -> every load/store is one coalesced 128B line.
// Forward scan kept in registers (fwd[64], fully unrolled); backward pass
// reconstructs x[t] = fwd[t] - 0.5*fwd[t-1] so x is read only once.
// No shared memory -> occupancy limited only by ~85 regs (~24 warps/SM).

#define S_DIM 2048
#define H_DIM 1024
#define CHUNK 64
#define HALO  24
#define NCH   (S_DIM / CHUNK)   // 32
#define TPB   256

__global__ __launch_bounds__(TPB, 2)
void decay_model_kernel(const float* __restrict__ x, float* __restrict__ out) {
    const int h  = blockIdx.x * TPB + threadIdx.x;   // h column (coalesced in warp)
    const int ci = blockIdx.y;                       // chunk index along S
    const int s0 = ci * CHUNK;
    const size_t base = (size_t)blockIdx.z * S_DIM * H_DIM + h;
    const float* __restrict__ xc = x + base;
    float* __restrict__ oc = out + base;

    // ---- Left-halo warmup (skipped for first chunk: contributions are zero) ----
    float y = 0.0f;
    if (ci != 0) {
        #pragma unroll
        for (int t = 0; t < HALO; ++t)
            y = fmaf(y, 0.5f, xc[(size_t)(s0 - HALO + t) * H_DIM]);
    }
    const float y_left = y;

    // ---- Forward scan, register resident ----
    float fwd[CHUNK];
    #pragma unroll
    for (int t = 0; t < CHUNK; ++t) {
        y = fmaf(y, 0.5f, xc[(size_t)(s0 + t) * H_DIM]);
        fwd[t] = y;
    }

    // ---- Right-halo warmup (skipped for last chunk) ----
    float z = 0.0f;
    if (ci != NCH - 1) {
        #pragma unroll
        for (int t = HALO - 1; t >= 0; --t)
            z = fmaf(z, 0.5f, xc[(size_t)(s0 + CHUNK + t) * H_DIM]);
    }

    // ---- Backward scan + combine + normalize + store ----
    // x[t] reconstructed from fwd[]: x[t] = fwd[t] - 0.5*fwd[t-1] (1-ulp noise).
    if (ci == 0 || ci == NCH - 1) {
        // Boundary chunks: exact norm (exp2f only here; 2 of 32 chunks).
        #pragma unroll
        for (int t = CHUNK - 1; t >= 0; --t) {
            float prev = (t > 0) ? fwd[t - 1] : y_left;
            float xv = fmaf(-0.5f, prev, fwd[t]);
            z = fmaf(z, 0.5f, xv);
            int s = s0 + t;
            float norm = 4.0f - exp2f(-(float)s) - exp2f(-(float)(S_DIM - 1 - s));
            oc[(size_t)s * H_DIM] = (fwd[t] + z) / norm;
        }
    } else {
        // Interior: norm == 4.0f exactly in fp32.
        #pragma unroll
        for (int t = CHUNK - 1; t >= 0; --t) {
            float prev = (t > 0) ? fwd[t - 1] : y_left;
            float xv = fmaf(-0.5f, prev, fwd[t]);
            z = fmaf(z, 0.5f, xv);
            oc[(size_t)(s0 + t) * H_DIM] = (fwd[t] + z) * 0.25f;
        }
    }
}

extern "C" void kernel_launch(void* const* d_in, const int* in_sizes, int n_in,
                              void* d_out, int out_size) {
    const float* x = (const float*)d_in[0];
    float* out = (float*)d_out;
    const int B = in_sizes[0] / (S_DIM * H_DIM);

    dim3 grid(H_DIM / TPB, NCH, B);   // (4, 32, B) = 2048 blocks of 256 threads
    decay_model_kernel<<<grid, TPB>>>(x, out);
}